// round 5
// baseline (speedup 1.0000x reference)
#include <cuda_runtime.h>

typedef unsigned long long ull;

#define Bn  16
#define ICn 3
#define QCn 8
#define VCn 16
#define Hn  224
#define Wn  224
#define H2  112

// ---- scratch: device globals (no runtime allocation allowed) ----
__device__ float g_q [Bn*24*H2*H2];          // [b][i*8+qc][112][112]
__device__ float g_v [Bn*16*H2*H2];          // [b][vc][112][112]
__device__ float g_S [1152*784];             // [(b,i,qc,c)][pq*49+uv]
__device__ float g_Qs[Bn*ICn*QCn*16];        // [(b,i,qc)][pq]
__device__ float g_a [Bn*ICn*VCn*16];        // [(b,i)][vc*16+pq]

#define FMA2(d,a,b) asm("fma.rn.f32x2 %0, %1, %2, %0;" : "+l"(d) : "l"(a), "l"(b))

// ===========================================================================
// Kernel A: fused static convs q (24 ch) + v (16 ch), stride 2, pad 3.
// grid (112 oy, 16 b), 224 threads = 2 halves x 112 ox, 20 out-ch each.
// ===========================================================================
__global__ __launch_bounds__(224) void k_convqv(
    const float* __restrict__ x,
    const float* __restrict__ Wq, const float* __restrict__ bq,
    const float* __restrict__ Wv, const float* __restrict__ bv)
{
    __shared__ float xs[3*7*232];
    __shared__ __align__(16) float ws[147*40];   // [cuv][oc]
    __shared__ float bs[40];
    const int oy = blockIdx.x, b = blockIdx.y;
    const int tid = threadIdx.x;

    for (int t = tid; t < 24*147; t += 224) { int oc=t/147, cuv=t%147; ws[cuv*40+oc]      = Wq[t]; }
    for (int t = tid; t < 16*147; t += 224) { int oc=t/147, cuv=t%147; ws[cuv*40+24+oc]   = Wv[t]; }
    if (tid < 24) bs[tid] = bq[tid];
    else if (tid < 40) bs[tid] = bv[tid-24];

    const float* xb = x + b*ICn*Hn*Wn;
    for (int t = tid; t < 3*7*232; t += 224) {
        int cc = t/(7*232), r = (t/232)%7, j = t%232;
        int row = 2*oy - 3 + r, col = j - 3;
        float v = 0.f;
        if (row >= 0 && row < Hn && col >= 0 && col < Wn) v = xb[(cc*Hn+row)*Wn + col];
        xs[t] = v;
    }
    __syncthreads();

    const int half = tid/112, ox = tid%112;
    float acc[20];
    #pragma unroll
    for (int k = 0; k < 20; k++) acc[k] = bs[half*20 + k];

    #pragma unroll 1
    for (int cc = 0; cc < 3; cc++)
      #pragma unroll 1
      for (int u = 0; u < 7; u++) {
        const float* xr = &xs[(cc*7+u)*232 + 2*ox];
        const float* wr = &ws[(cc*49+u*7)*40 + half*20];
        #pragma unroll
        for (int v = 0; v < 7; v++) {
            float xv = xr[v];
            #pragma unroll
            for (int k4 = 0; k4 < 5; k4++) {
                float4 w4 = *reinterpret_cast<const float4*>(&wr[v*40 + k4*4]);
                acc[k4*4+0] += xv*w4.x; acc[k4*4+1] += xv*w4.y;
                acc[k4*4+2] += xv*w4.z; acc[k4*4+3] += xv*w4.w;
            }
        }
      }

    #pragma unroll
    for (int k = 0; k < 20; k++) {
        int oc = half*20 + k;
        if (oc < 24) g_q[((b*24 + oc)*H2 + oy)*H2 + ox]      = acc[k];
        else         g_v[((b*16 + (oc-24))*H2 + oy)*H2 + ox] = acc[k];
    }
}

// ===========================================================================
// Kernel S (heavy): S[pq][uv] = sum_{ky,kx} q_pad[2p-3+ky][2q-3+kx]*x_pad[2ky-3+u][2kx-3+v]
// grid 1152 = (b,i,qc,c); 128 thr = 4 warps (ky-groups of 28) x 32 lanes.
// lane -> (u=lane/4 clamped to 6, qq=lane%4); tile 4p x 8v via f32x2.
// ===========================================================================
__global__ __launch_bounds__(128) void k_S(const float* __restrict__ x)
{
    __shared__ union SM {
        struct { float2 q[4][4][120]; float xx[4][7][232]; } m;  // 41344 B
        float red[3584];
    } sm;

    const int bx = blockIdx.x;
    const int c = bx%3, qc = (bx/3)%8, i = (bx/24)%3, b = bx/72;
    const float* qb = g_q + ((b*3 + i)*8 + qc)*H2*H2;
    const float* xb = x   + (b*3 + c)*Hn*Wn;

    const int tid = threadIdx.x, g = tid >> 5, lane = tid & 31;
    int u = lane >> 2; if (u > 6) u = 6;
    const int qq = lane & 3;

    ull acc[4][4];
    #pragma unroll
    for (int p = 0; p < 4; p++)
      #pragma unroll
      for (int j = 0; j < 4; j++) acc[p][j] = 0ull;

    for (int t = 0; t < 28; t++) {
        const int ky = g*28 + t;
        __syncwarp();                               // WAR on per-warp smem
        #pragma unroll
        for (int p = 0; p < 4; p++) {
            int r = ky + 2*p - 3;
            bool rok = (r >= 0 && r < H2);
            const float* qr = qb + r*H2;
            for (int j = lane; j < 118; j += 32) {
                float v = 0.f;
                if (rok && j >= 3 && j < 115) v = qr[j-3];
                sm.m.q[g][p][j] = make_float2(v, v);
            }
        }
        #pragma unroll
        for (int uu = 0; uu < 7; uu++) {
            int r = 2*ky - 3 + uu;
            bool rok = (r >= 0 && r < Hn);
            const float* xr = xb + r*Wn;
            for (int j = lane; j < 230; j += 32) {
                float v = 0.f;
                if (rok && j >= 3 && j < 227) v = xr[j-3];
                sm.m.xx[g][uu][j] = v;
            }
        }
        __syncwarp();                               // RAW

        const float* xrow = sm.m.xx[g][u];
        const float2* q0 = sm.m.q[g][0]; const float2* q1 = sm.m.q[g][1];
        const float2* q2 = sm.m.q[g][2]; const float2* q3 = sm.m.q[g][3];
        #pragma unroll 2
        for (int kx = 0; kx < 112; kx++) {
            ull qd[4], xv[4];
            qd[0] = *reinterpret_cast<const ull*>(q0 + kx + 2*qq);
            qd[1] = *reinterpret_cast<const ull*>(q1 + kx + 2*qq);
            qd[2] = *reinterpret_cast<const ull*>(q2 + kx + 2*qq);
            qd[3] = *reinterpret_cast<const ull*>(q3 + kx + 2*qq);
            #pragma unroll
            for (int j = 0; j < 4; j++)
                xv[j] = *reinterpret_cast<const ull*>(&xrow[2*kx + 2*j]);
            #pragma unroll
            for (int p = 0; p < 4; p++)
              #pragma unroll
              for (int j = 0; j < 4; j++) FMA2(acc[p][j], qd[p], xv[j]);
        }
    }

    __syncthreads();                                // before aliasing red
    if (lane < 28) {
        #pragma unroll
        for (int p = 0; p < 4; p++) {
            int pq = p*4 + qq;
            #pragma unroll
            for (int j = 0; j < 4; j++) {
                float2 f = *reinterpret_cast<float2*>(&acc[p][j]);
                sm.red[((g*16+pq)*7+u)*8 + 2*j    ] = f.x;
                sm.red[((g*16+pq)*7+u)*8 + 2*j + 1] = f.y;  // v=7 slot: garbage, never read
            }
        }
    }
    __syncthreads();

    float* So = g_S + bx*784;
    for (int o = tid; o < 784; o += 128) {
        int pq = o/49, uv = o%49, uu = uv/7, vv = uv%7;
        float s = 0.f;
        #pragma unroll
        for (int gg = 0; gg < 4; gg++) s += sm.red[((gg*16+pq)*7+uu)*8 + vv];
        So[o] = s;
    }
}

// ===========================================================================
// Kernel Qs: clipped window sums of q for the bk bias term. grid 384 = (b,i,qc)
// ===========================================================================
__global__ __launch_bounds__(128) void k_qs()
{
    __shared__ float cs[4][114];
    const int bx = blockIdx.x;
    const float* Q = g_q + bx*H2*H2;
    const int tid = threadIdx.x;
    if (tid < 112) {
        float full=0.f, e0=0.f,e1=0.f,e2=0.f,e109=0.f,e110=0.f,e111=0.f;
        for (int y = 0; y < 112; y++) {
            float v = Q[y*H2 + tid];
            full += v;
            if (y==0) e0=v; else if (y==1) e1=v; else if (y==2) e2=v;
            else if (y==109) e109=v; else if (y==110) e110=v; else if (y==111) e111=v;
        }
        cs[0][tid] = full - e109 - e110 - e111;   // p=0: rows [0,109)
        cs[1][tid] = full - e111;                 // p=1: rows [0,111)
        cs[2][tid] = full - e0;                   // p=2: rows [1,112)
        cs[3][tid] = full - e0 - e1 - e2;         // p=3: rows [3,112)
    }
    __syncthreads();
    if (tid < 16) {
        int p = tid >> 2, qx = tid & 3;
        int xs_ = (qx <= 1) ? 0 : (qx == 2 ? 1 : 3);
        int xe_ = (qx == 0) ? 109 : (qx == 1 ? 111 : 112);
        float s = 0.f;
        for (int xc = xs_; xc < xe_; xc++) s += cs[p][xc];
        g_Qs[bx*16 + tid] = s;
    }
}

// ===========================================================================
// Kernel a: a = sum_{qc,c,uv} Wk*S + sum_qc bk*Qsum.  grid 48 = (b,i)
// ===========================================================================
__global__ __launch_bounds__(256) void k_a(const float* __restrict__ Wk,
                                           const float* __restrict__ bk)
{
    const int bx = blockIdx.x;              // b*3+i
    const int i = bx % 3;
    const int tid = threadIdx.x;
    const int vc = tid >> 4, pq = tid & 15;
    const float* Sb = g_S + bx*24*784;
    const float* Wb = Wk + i*(VCn*QCn*ICn*49);
    float acc = 0.f;
    for (int qc = 0; qc < 8; qc++)
      for (int cc = 0; cc < 3; cc++) {
        const float* Sp = Sb + (qc*3+cc)*784 + pq*49;
        const float* Wp = Wb + ((vc*8+qc)*3+cc)*49;
        #pragma unroll
        for (int uv = 0; uv < 49; uv++) acc += Wp[uv]*Sp[uv];
      }
    const float* Qsb = g_Qs + bx*8*16;
    #pragma unroll
    for (int qc = 0; qc < 8; qc++)
        acc += bk[(i*16+vc)*8+qc] * Qsb[qc*16+pq];
    g_a[bx*256 + tid] = acc;                // tid = vc*16+pq
}

// ===========================================================================
// Kernel o: o[b,i,58,58] = dynconv(v[b], a[b,i]) stride 2 pad 3, 4x4 kernel
// ===========================================================================
__global__ __launch_bounds__(256) void k_o(float* __restrict__ out)
{
    __shared__ float as_[256];
    const int bx = blockIdx.x;              // b*3+i
    const int b = bx/3;
    const int tid = threadIdx.x;
    as_[tid] = g_a[bx*256 + tid];
    __syncthreads();

    const float* vb = g_v + b*16*H2*H2;
    for (int idx = tid; idx < 58*58; idx += 256) {
        int oy = idx/58, ox = idx%58;
        float acc = 0.f;
        for (int vc = 0; vc < 16; vc++) {
            const float* vp = vb + vc*H2*H2;
            const float* ap = &as_[vc*16];
            #pragma unroll
            for (int ky = 0; ky < 4; ky++) {
                int r = 2*oy - 3 + ky;
                if (r < 0 || r >= H2) continue;
                #pragma unroll
                for (int kx = 0; kx < 4; kx++) {
                    int cc = 2*ox - 3 + kx;
                    if (cc < 0 || cc >= H2) continue;
                    acc += ap[ky*4+kx] * vp[r*H2 + cc];
                }
            }
        }
        out[bx*3364 + idx] = acc;
    }
}

extern "C" void kernel_launch(void* const* d_in, const int* in_sizes, int n_in,
                              void* d_out, int out_size)
{
    const float* x  = (const float*)d_in[0];
    const float* Wq = (const float*)d_in[1];
    const float* bq = (const float*)d_in[2];
    const float* Wk = (const float*)d_in[3];
    const float* bk = (const float*)d_in[4];
    const float* Wv = (const float*)d_in[5];
    const float* bv = (const float*)d_in[6];
    float* out = (float*)d_out;

    k_convqv<<<dim3(112,16), 224>>>(x, Wq, bq, Wv, bv);
    k_S     <<<1152, 128>>>(x);
    k_qs    <<<384, 128>>>();
    k_a     <<<48, 256>>>(Wk, bk);
    k_o     <<<48, 256>>>(out);
}

// round 6
// speedup vs baseline: 1.1601x; 1.1601x over previous
#include <cuda_runtime.h>

typedef unsigned long long ull;

#define Bn  16
#define ICn 3
#define QCn 8
#define VCn 16
#define Hn  224
#define Wn  224
#define H2  112

// ---- scratch: device globals (no runtime allocation allowed) ----
__device__ float g_q [Bn*24*H2*H2];          // [b][i*8+qc][112][112]
__device__ float g_v [Bn*16*H2*H2];          // [b][vc][112][112]
__device__ float g_S [1152*784];             // [(b,i,qc,c)][pq*49+uv]
__device__ float g_Qs[Bn*ICn*QCn*16];        // [(b,i,qc)][pq]
__device__ float g_a [Bn*ICn*VCn*16];        // [(b,i)][vc*16+pq]

#define FMA2(d,a,b) asm("fma.rn.f32x2 %0, %1, %2, %0;" : "+l"(d) : "l"(a), "l"(b))
#define DUP2(d,s)   asm("mov.b64 %0, {%1, %1};" : "=l"(d) : "f"(s))

// ===========================================================================
// Kernel A: fused static convs q (24 ch) + v (16 ch), stride 2, pad 3.
// grid (112 oy, 16 b), 224 threads = 2 halves x 112 ox, 20 out-ch each.
// f32x2 accumulators: 10 FMA2 per input tap instead of 20 FFMA.
// ===========================================================================
__global__ __launch_bounds__(224) void k_convqv(
    const float* __restrict__ x,
    const float* __restrict__ Wq, const float* __restrict__ bq,
    const float* __restrict__ Wv, const float* __restrict__ bv)
{
    __shared__ __align__(16) float xs[3*7*232];
    __shared__ __align__(16) float ws[147*40];   // [cuv][oc]
    __shared__ __align__(16) float bs[40];
    const int oy = blockIdx.x, b = blockIdx.y;
    const int tid = threadIdx.x;

    for (int t = tid; t < 24*147; t += 224) { int oc=t/147, cuv=t%147; ws[cuv*40+oc]      = Wq[t]; }
    for (int t = tid; t < 16*147; t += 224) { int oc=t/147, cuv=t%147; ws[cuv*40+24+oc]   = Wv[t]; }
    if (tid < 24) bs[tid] = bq[tid];
    else if (tid < 40) bs[tid] = bv[tid-24];

    const float* xb = x + b*ICn*Hn*Wn;
    for (int t = tid; t < 3*7*232; t += 224) {
        int cc = t/(7*232), r = (t/232)%7, j = t%232;
        int row = 2*oy - 3 + r, col = j - 3;
        float v = 0.f;
        if (row >= 0 && row < Hn && col >= 0 && col < Wn) v = xb[(cc*Hn+row)*Wn + col];
        xs[t] = v;
    }
    __syncthreads();

    const int half = tid/112, ox = tid%112;
    ull acc2[10];
    {
        const float2* b2 = reinterpret_cast<const float2*>(bs + half*20);
        #pragma unroll
        for (int k = 0; k < 10; k++) {
            float2 t = b2[k];
            asm("mov.b64 %0, {%1, %2};" : "=l"(acc2[k]) : "f"(t.x), "f"(t.y));
        }
    }

    #pragma unroll 1
    for (int cc = 0; cc < 3; cc++)
      #pragma unroll 1
      for (int u = 0; u < 7; u++) {
        const float* xr = &xs[(cc*7+u)*232 + 2*ox];
        const ull*  wr = reinterpret_cast<const ull*>(&ws[(cc*49+u*7)*40 + half*20]);
        #pragma unroll
        for (int v = 0; v < 7; v++) {
            ull xd; DUP2(xd, xr[v]);
            #pragma unroll
            for (int k = 0; k < 10; k++) FMA2(acc2[k], xd, wr[v*20 + k]);
        }
      }

    #pragma unroll
    for (int k = 0; k < 10; k++) {
        float2 f = *reinterpret_cast<float2*>(&acc2[k]);
        int oc0 = half*20 + 2*k;
        #pragma unroll
        for (int h = 0; h < 2; h++) {
            int oc = oc0 + h;
            float val = h ? f.y : f.x;
            if (oc < 24) g_q[((b*24 + oc)*H2 + oy)*H2 + ox]      = val;
            else         g_v[((b*16 + (oc-24))*H2 + oy)*H2 + ox] = val;
        }
    }
}

// ===========================================================================
// Kernel S (heavy): S[pq][uv] = sum_{ky,kx} q_pad[2p-3+ky][2q-3+kx]*x_pad[2ky-3+u][2kx-3+v]
// grid 1152 = (b,i,qc,c); 128 thr = 4 warps (ky-groups of 28) x 32 lanes.
// lane -> (u=lane/4 clamped to 6, qq=lane%4); tile 4p x 8v via f32x2.
// Sliding-window x in registers: 4 q-LDS + 1 x-LDS + 16 FMA2 per kx.
// ===========================================================================
__global__ __launch_bounds__(128) void k_S(const float* __restrict__ x)
{
    __shared__ union SM {
        struct { float2 q[4][4][120]; float xx[4][7][232]; } m;  // 41344 B
        float red[3584];
    } sm;

    const int bx = blockIdx.x;
    const int c = bx%3, qc = (bx/3)%8, i = (bx/24)%3, b = bx/72;
    const float* qb = g_q + ((b*3 + i)*8 + qc)*H2*H2;
    const float* xb = x   + (b*3 + c)*Hn*Wn;

    const int tid = threadIdx.x, g = tid >> 5, lane = tid & 31;
    int u = lane >> 2; if (u > 6) u = 6;
    const int qq = lane & 3;

    ull acc[4][4];
    #pragma unroll
    for (int p = 0; p < 4; p++)
      #pragma unroll
      for (int j = 0; j < 4; j++) acc[p][j] = 0ull;

    for (int t = 0; t < 28; t++) {
        const int ky = g*28 + t;
        __syncwarp();                               // WAR on per-warp smem
        #pragma unroll
        for (int p = 0; p < 4; p++) {
            int r = ky + 2*p - 3;
            bool rok = (r >= 0 && r < H2);
            const float* qr = qb + r*H2;
            for (int j = lane; j < 118; j += 32) {
                float v = 0.f;
                if (rok && j >= 3 && j < 115) v = qr[j-3];
                sm.m.q[g][p][j] = make_float2(v, v);
            }
        }
        #pragma unroll
        for (int uu = 0; uu < 7; uu++) {
            int r = 2*ky - 3 + uu;
            bool rok = (r >= 0 && r < Hn);
            const float* xr = xb + r*Wn;
            for (int j = lane; j < 230; j += 32) {
                float v = 0.f;
                if (rok && j >= 3 && j < 227) v = xr[j-3];
                sm.m.xx[g][uu][j] = v;
            }
        }
        __syncwarp();                               // RAW

        // word-indexed smem views (8B aligned: struct offsets are multiples of 8)
        const ull* xrow = reinterpret_cast<const ull*>(sm.m.xx[g][u]);   // words 0..115
        const ull* qp0 = reinterpret_cast<const ull*>(sm.m.q[g][0]) + 2*qq;
        const ull* qp1 = reinterpret_cast<const ull*>(sm.m.q[g][1]) + 2*qq;
        const ull* qp2 = reinterpret_cast<const ull*>(sm.m.q[g][2]) + 2*qq;
        const ull* qp3 = reinterpret_cast<const ull*>(sm.m.q[g][3]) + 2*qq;

        ull xw[4] = { xrow[0], xrow[1], xrow[2], xrow[3] };
        #pragma unroll 1
        for (int k4 = 0; k4 < 112; k4 += 4) {
            #pragma unroll
            for (int r = 0; r < 4; r++) {
                const int kx = k4 + r;
                ull qd0 = qp0[kx], qd1 = qp1[kx], qd2 = qp2[kx], qd3 = qp3[kx];
                #pragma unroll
                for (int j = 0; j < 4; j++) {
                    ull xv = xw[(r + j) & 3];       // word kx+j
                    FMA2(acc[0][j], qd0, xv);
                    FMA2(acc[1][j], qd1, xv);
                    FMA2(acc[2][j], qd2, xv);
                    FMA2(acc[3][j], qd3, xv);
                }
                xw[r & 3] = xrow[kx + 4];           // max index 115: in bounds
            }
        }
    }

    __syncthreads();                                // before aliasing red
    if (lane < 28) {
        #pragma unroll
        for (int p = 0; p < 4; p++) {
            int pq = p*4 + qq;
            #pragma unroll
            for (int j = 0; j < 4; j++) {
                float2 f = *reinterpret_cast<float2*>(&acc[p][j]);
                sm.red[((g*16+pq)*7+u)*8 + 2*j    ] = f.x;
                sm.red[((g*16+pq)*7+u)*8 + 2*j + 1] = f.y;  // v=7 slot: garbage, never read
            }
        }
    }
    __syncthreads();

    float* So = g_S + bx*784;
    for (int o = tid; o < 784; o += 128) {
        int pq = o/49, uv = o%49, uu = uv/7, vv = uv%7;
        float s = 0.f;
        #pragma unroll
        for (int gg = 0; gg < 4; gg++) s += sm.red[((gg*16+pq)*7+uu)*8 + vv];
        So[o] = s;
    }
}

// ===========================================================================
// Kernel Qs: clipped window sums of q for the bk bias term. grid 384 = (b,i,qc)
// ===========================================================================
__global__ __launch_bounds__(128) void k_qs()
{
    __shared__ float cs[4][114];
    const int bx = blockIdx.x;
    const float* Q = g_q + bx*H2*H2;
    const int tid = threadIdx.x;
    if (tid < 112) {
        float full=0.f, e0=0.f,e1=0.f,e2=0.f,e109=0.f,e110=0.f,e111=0.f;
        for (int y = 0; y < 112; y++) {
            float v = Q[y*H2 + tid];
            full += v;
            if (y==0) e0=v; else if (y==1) e1=v; else if (y==2) e2=v;
            else if (y==109) e109=v; else if (y==110) e110=v; else if (y==111) e111=v;
        }
        cs[0][tid] = full - e109 - e110 - e111;   // p=0: rows [0,109)
        cs[1][tid] = full - e111;                 // p=1: rows [0,111)
        cs[2][tid] = full - e0;                   // p=2: rows [1,112)
        cs[3][tid] = full - e0 - e1 - e2;         // p=3: rows [3,112)
    }
    __syncthreads();
    if (tid < 16) {
        int p = tid >> 2, qx = tid & 3;
        int xs_ = (qx <= 1) ? 0 : (qx == 2 ? 1 : 3);
        int xe_ = (qx == 0) ? 109 : (qx == 1 ? 111 : 112);
        float s = 0.f;
        for (int xc = xs_; xc < xe_; xc++) s += cs[p][xc];
        g_Qs[bx*16 + tid] = s;
    }
}

// ===========================================================================
// Kernel a: a = sum_{qc,c,uv} Wk*S + sum_qc bk*Qsum.
// grid 768 = (b,i,vc); 256 thr = 16 K-slices x 16 pq, shfl-reduced.
// ===========================================================================
__global__ __launch_bounds__(256) void k_a(const float* __restrict__ Wk,
                                           const float* __restrict__ bk)
{
    const int bx = blockIdx.x;              // (b*3+i)*16 + vc
    const int vc = bx & 15, bi = bx >> 4;
    const int i = bi % 3;
    const int tid = threadIdx.x;
    const int s = tid & 15, pq = tid >> 4;
    const float* Sb = g_S + bi*24*784;
    const float* Wb = Wk + i*(VCn*QCn*ICn*49) + vc*(QCn*ICn*49);
    float acc = 0.f;
    #pragma unroll 1
    for (int qcc = 0; qcc < 24; qcc++) {
        const float* Sp = Sb + qcc*784 + pq*49;
        const float* Wp = Wb + qcc*49;
        #pragma unroll
        for (int uv = s; uv < 49; uv += 16) acc += Wp[uv]*Sp[uv];
    }
    // reduce over s within each 16-lane segment
    #pragma unroll
    for (int o = 8; o; o >>= 1) acc += __shfl_down_sync(0xffffffffu, acc, o, 16);
    if (s == 0) {
        const float* Qsb = g_Qs + bi*8*16;
        float bterm = 0.f;
        #pragma unroll
        for (int qc = 0; qc < 8; qc++)
            bterm += bk[(i*16+vc)*8+qc] * Qsb[qc*16+pq];
        g_a[bi*256 + vc*16 + pq] = acc + bterm;
    }
}

// ===========================================================================
// Kernel o: o[b,i,58,58] = dynconv(v[b], a[b,i]) stride 2 pad 3, 4x4 kernel
// grid (48, 14) — one 256-output chunk per (bx, chunk) block.
// ===========================================================================
__global__ __launch_bounds__(256) void k_o(float* __restrict__ out)
{
    __shared__ float as_[256];
    const int bx = blockIdx.x;              // b*3+i
    const int b = bx/3;
    const int tid = threadIdx.x;
    as_[tid] = g_a[bx*256 + tid];
    __syncthreads();

    const int idx = blockIdx.y*256 + tid;
    if (idx >= 58*58) return;
    const int oy = idx/58, ox = idx%58;
    const float* vb = g_v + b*16*H2*H2;
    float acc = 0.f;
    for (int vc = 0; vc < 16; vc++) {
        const float* vp = vb + vc*H2*H2;
        const float* ap = &as_[vc*16];
        #pragma unroll
        for (int ky = 0; ky < 4; ky++) {
            int r = 2*oy - 3 + ky;
            if (r < 0 || r >= H2) continue;
            #pragma unroll
            for (int kx = 0; kx < 4; kx++) {
                int cc = 2*ox - 3 + kx;
                if (cc < 0 || cc >= H2) continue;
                acc += ap[ky*4+kx] * vp[r*H2 + cc];
            }
        }
    }
    out[bx*3364 + idx] = acc;
}

extern "C" void kernel_launch(void* const* d_in, const int* in_sizes, int n_in,
                              void* d_out, int out_size)
{
    const float* x  = (const float*)d_in[0];
    const float* Wq = (const float*)d_in[1];
    const float* bq = (const float*)d_in[2];
    const float* Wk = (const float*)d_in[3];
    const float* bk = (const float*)d_in[4];
    const float* Wv = (const float*)d_in[5];
    const float* bv = (const float*)d_in[6];
    float* out = (float*)d_out;

    k_convqv<<<dim3(112,16), 224>>>(x, Wq, bq, Wv, bv);
    k_S     <<<1152, 128>>>(x);
    k_qs    <<<384, 128>>>();
    k_a     <<<768, 256>>>(Wk, bk);
    k_o     <<<dim3(48,14), 256>>>(out);
}

// round 11
// speedup vs baseline: 1.6855x; 1.4529x over previous
#include <cuda_runtime.h>
#include <cuda_bf16.h>
#include <stdint.h>

typedef unsigned long long ull;

#define Bn  16
#define ICn 3
#define QCn 8
#define VCn 16
#define Hn  224
#define Wn  224
#define H2  112

// ---- scratch: device globals (no runtime allocation allowed) ----
__device__ float g_q [Bn*24*H2*H2];          // [b][i*8+qc][112][112]
__device__ float g_v [Bn*16*H2*H2];          // [b][vc][112][112]
__device__ float g_S [1152*784];             // [(b,i,qc,c)][pq*49+uv]
__device__ float g_Qs[Bn*ICn*QCn*16];        // [(b,i,qc)][pq]
__device__ float g_a [Bn*ICn*VCn*16];        // [(b,i)][vc*16+pq]
// bf16 hi/lo split, padded rows (col pad of 3 baked in); 16B-aligned for uint4 IO
__device__ __align__(16) __nv_bfloat16 g_qh[384*112*120];
__device__ __align__(16) __nv_bfloat16 g_ql[384*112*120];
__device__ __align__(16) __nv_bfloat16 g_xh[48*224*232];
__device__ __align__(16) __nv_bfloat16 g_xl[48*224*232];

#define FMA2(d,a,b) asm("fma.rn.f32x2 %0, %1, %2, %0;" : "+l"(d) : "l"(a), "l"(b))
#define DUP2(d,s)   asm("mov.b64 %0, {%1, %1};" : "=l"(d) : "f"(s))

__device__ __forceinline__ uint32_t smem_to_u32(const void* p) {
    uint32_t a;
    asm("{ .reg .u64 t; cvta.to.shared.u64 t, %1; cvt.u32.u64 %0, t; }" : "=r"(a) : "l"(p));
    return a;
}

#define LDSM_X4(r0,r1,r2,r3,addr) \
    asm volatile("ldmatrix.sync.aligned.m8n8.x4.shared.b16 {%0,%1,%2,%3}, [%4];" \
        : "=r"(r0),"=r"(r1),"=r"(r2),"=r"(r3) : "r"(addr))

#define MMA16816(d,a,b0,b1) \
    asm volatile("mma.sync.aligned.m16n8k16.row.col.f32.bf16.bf16.f32 " \
        "{%0,%1,%2,%3}, {%4,%5,%6,%7}, {%8,%9}, {%0,%1,%2,%3};" \
        : "+f"((d)[0]),"+f"((d)[1]),"+f"((d)[2]),"+f"((d)[3]) \
        : "r"((a)[0]),"r"((a)[1]),"r"((a)[2]),"r"((a)[3]), "r"(b0),"r"(b1))

// ===========================================================================
// Kernel A: fused static convs q (24 ch) + v (16 ch), stride 2, pad 3.
// ===========================================================================
__global__ __launch_bounds__(224) void k_convqv(
    const float* __restrict__ x,
    const float* __restrict__ Wq, const float* __restrict__ bq,
    const float* __restrict__ Wv, const float* __restrict__ bv)
{
    __shared__ __align__(16) float xs[3*7*232];
    __shared__ __align__(16) float ws[147*40];
    __shared__ __align__(16) float bs[40];
    const int oy = blockIdx.x, b = blockIdx.y;
    const int tid = threadIdx.x;

    for (int t = tid; t < 24*147; t += 224) { int oc=t/147, cuv=t%147; ws[cuv*40+oc]    = Wq[t]; }
    for (int t = tid; t < 16*147; t += 224) { int oc=t/147, cuv=t%147; ws[cuv*40+24+oc] = Wv[t]; }
    if (tid < 24) bs[tid] = bq[tid];
    else if (tid < 40) bs[tid] = bv[tid-24];

    const float* xb = x + b*ICn*Hn*Wn;
    for (int t = tid; t < 3*7*232; t += 224) {
        int cc = t/(7*232), r = (t/232)%7, j = t%232;
        int row = 2*oy - 3 + r, col = j - 3;
        float v = 0.f;
        if (row >= 0 && row < Hn && col >= 0 && col < Wn) v = xb[(cc*Hn+row)*Wn + col];
        xs[t] = v;
    }
    __syncthreads();

    const int half = tid/112, ox = tid%112;
    ull acc2[10];
    {
        const float2* b2 = reinterpret_cast<const float2*>(bs + half*20);
        #pragma unroll
        for (int k = 0; k < 10; k++) {
            float2 t = b2[k];
            asm("mov.b64 %0, {%1, %2};" : "=l"(acc2[k]) : "f"(t.x), "f"(t.y));
        }
    }
    #pragma unroll 1
    for (int cc = 0; cc < 3; cc++)
      #pragma unroll 1
      for (int u = 0; u < 7; u++) {
        const float* xr = &xs[(cc*7+u)*232 + 2*ox];
        const ull*  wr = reinterpret_cast<const ull*>(&ws[(cc*49+u*7)*40 + half*20]);
        #pragma unroll
        for (int v = 0; v < 7; v++) {
            ull xd; DUP2(xd, xr[v]);
            #pragma unroll
            for (int k = 0; k < 10; k++) FMA2(acc2[k], xd, wr[v*20 + k]);
        }
      }
    #pragma unroll
    for (int k = 0; k < 10; k++) {
        float2 f = *reinterpret_cast<float2*>(&acc2[k]);
        int oc0 = half*20 + 2*k;
        #pragma unroll
        for (int h = 0; h < 2; h++) {
            int oc = oc0 + h;
            float val = h ? f.y : f.x;
            if (oc < 24) g_q[((b*24 + oc)*H2 + oy)*H2 + ox]      = val;
            else         g_v[((b*16 + (oc-24))*H2 + oy)*H2 + ox] = val;
        }
    }
}

// ===========================================================================
// Pre-pass converts: f32 -> padded bf16 hi/lo
// ===========================================================================
__global__ __launch_bounds__(256) void k_cvt_q()
{
    const int bx = blockIdx.x;               // 384 = (b, i*8+qc)
    const float* Q = g_q + bx*H2*H2;
    __nv_bfloat16* oh = g_qh + bx*112*120;
    __nv_bfloat16* ol = g_ql + bx*112*120;
    for (int t = threadIdx.x; t < 112*120; t += 256) {
        int y = t/120, j = t%120;
        float v = (j >= 3 && j < 115) ? Q[y*H2 + (j-3)] : 0.f;
        __nv_bfloat16 h = __float2bfloat16(v);
        oh[t] = h;
        ol[t] = __float2bfloat16(v - __bfloat162float(h));
    }
}

__global__ __launch_bounds__(256) void k_cvt_x(const float* __restrict__ x)
{
    const int bx = blockIdx.x;               // 48 = (b, c)
    const float* X = x + bx*Hn*Wn;
    __nv_bfloat16* oh = g_xh + bx*224*232;
    __nv_bfloat16* ol = g_xl + bx*224*232;
    for (int t = threadIdx.x; t < 224*232; t += 256) {
        int y = t/232, j = t%232;
        float v = (j >= 3 && j < 227) ? X[y*Wn + (j-3)] : 0.f;
        __nv_bfloat16 h = __float2bfloat16(v);
        oh[t] = h;
        ol[t] = __float2bfloat16(v - __bfloat162float(h));
    }
}

// ===========================================================================
// Kernel S via mma.sync (sm_80-class HMMA, valid on plain sm_103):
// per (b,i,c): D[128,64] = A.B^T over K=(ky,kx)=12544, fp32 accum in regs.
//   A[(qc,p,q'), kx] = q_pad_row[2q' + kx]   (hi/lo bf16)
//   B[(u,v), kx]     = x_pad_row_u[2kx + v]  (hi/lo bf16)
// Valid (u,v): u in 0..6, v in 0..6. Rows with u==7 or v==7 are dead (never
// built, never read back); their D columns are ignored.
// 3 split passes: AhBh + AhBl + AlBh.
// Tiles: row-major 256B rows, 16B-chunk XOR swizzle (ch ^ (row&7)).
// ===========================================================================
#define SM_AH    0
#define SM_AL    32768
#define SM_BH    65536
#define SM_BL    81920
#define SM_QS    98304        // qs_h[32][120]bf16 then qs_l (7680 B each)
#define SM_XS    113664       // xs_h[7][232]bf16 then xs_l  (3248 B each)
#define SM_TOT   120160

extern __shared__ char dsm[];

__global__ __launch_bounds__(256) void k_S_mma()
{
    const uint32_t smem = smem_to_u32(dsm);
    const int tid = threadIdx.x, w = tid >> 5, lane = tid & 31;
    const int bx = blockIdx.x;               // 144 = (b,i,c), c fastest
    const int c = bx % 3, i = (bx/3) % 3, b = bx/9;

    const __nv_bfloat16* qhb = g_qh + ((b*3 + i)*8)*112*120;
    const __nv_bfloat16* qlb = g_ql + ((b*3 + i)*8)*112*120;
    const __nv_bfloat16* xhb = g_xh + (b*3 + c)*224*232;
    const __nv_bfloat16* xlb = g_xl + (b*3 + c)*224*232;

    float acc[8][4];
    #pragma unroll
    for (int n = 0; n < 8; n++)
      #pragma unroll
      for (int e = 0; e < 4; e++) acc[n][e] = 0.f;

    // per-thread ldmatrix address components
    const int rA = w*16 + (lane & 15);           // A row for this thread
    const uint32_t aArbH = smem + SM_AH + rA*256;
    const uint32_t aArbL = smem + SM_AL + rA*256;
    const uint32_t aArx  = (rA & 7)*16;
    const int hA = (lane >> 4) & 1;              // A chunk half
    const int rBo = (lane & 7) + ((lane & 16) >> 1);  // B row offset within 16
    const uint32_t bBrx = (lane & 7)*16;
    const int hB = (lane >> 3) & 1;              // B chunk half

    for (int ky = 0; ky < 112; ky++) {
        // ---- stage q rows: 32 (qc,p) rows x 15 u128 chunks x 2 mats
        for (int it = tid; it < 960; it += 256) {
            int mat = it >= 480; int idx = it - mat*480;
            int row = idx/15, ch = idx%15;       // row = qc*4 + p
            int p = row & 3, qc = row >> 2;
            int r = ky + 2*p - 3;
            uint4 val = make_uint4(0u,0u,0u,0u);
            if (r >= 0 && r < 112)
                val = reinterpret_cast<const uint4*>(
                    (mat ? qlb : qhb) + qc*(112*120) + r*120)[ch];
            *reinterpret_cast<uint4*>(dsm + SM_QS + mat*7680 + row*240 + ch*16) = val;
        }
        // ---- stage x rows: 7 rows x 29 chunks x 2 mats
        for (int it = tid; it < 406; it += 256) {
            int mat = it >= 203; int idx = it - mat*203;
            int u = idx/29, ch = idx%29;
            int r = 2*ky - 3 + u;
            uint4 val = make_uint4(0u,0u,0u,0u);
            if (r >= 0 && r < 224)
                val = reinterpret_cast<const uint4*>((mat ? xlb : xhb) + r*232)[ch];
            *reinterpret_cast<uint4*>(dsm + SM_XS + mat*3248 + u*464 + ch*16) = val;
        }
        __syncthreads();

        // ---- build A tiles: 128 rows x 14 chunks x 2 mats
        for (int it = tid; it < 3584; it += 256) {
            int mat = it >= 1792; int idx = it - mat*1792;
            int m = idx/14, ch = idx%14;
            int qc = m >> 4, p = (m >> 2) & 3, qp = m & 3;
            const uint32_t* src = reinterpret_cast<const uint32_t*>(
                dsm + SM_QS + mat*7680 + (qc*4 + p)*240);
            int w0 = ch*4 + qp;
            uint4 val = make_uint4(src[w0], src[w0+1], src[w0+2], src[w0+3]);
            int byte = m*256 + ((ch ^ (m & 7))*16);
            *reinterpret_cast<uint4*>(dsm + (mat ? SM_AL : SM_AH) + byte) = val;
        }
        // ---- build B tiles: only live rows (u<7, v<7); dead rows never read
        for (int it = tid; it < 1792; it += 256) {
            int mat = it >= 896; int idx = it - mat*896;
            int n = idx/14, ch = idx%14;
            int u = n >> 3, v = n & 7;
            if (u == 7 || v == 7) continue;      // dead row: u=7 would read OOB
            const uint32_t* src = reinterpret_cast<const uint32_t*>(
                dsm + SM_XS + mat*3248 + u*464);
            int w0 = ch*8 + (v >> 1);
            uint32_t sel = (v & 1) ? 0x7632u : 0x5410u;
            uint32_t p0 = __byte_perm(src[w0],   src[w0+1], sel);
            uint32_t p1 = __byte_perm(src[w0+2], src[w0+3], sel);
            uint32_t p2 = __byte_perm(src[w0+4], src[w0+5], sel);
            uint32_t p3 = __byte_perm(src[w0+6], src[w0+7], sel);
            int byte = n*256 + ((ch ^ (n & 7))*16);
            *reinterpret_cast<uint4*>(dsm + (mat ? SM_BL : SM_BH) + byte) =
                make_uint4(p0, p1, p2, p3);
        }
        __syncthreads();

        // ---- MMA: 7 k16-steps, 3 split passes
        #pragma unroll 1
        for (int ks = 0; ks < 7; ks++) {
            const uint32_t cA = (uint32_t)(2*ks + hA)*16;
            uint32_t ah[4], al[4];
            LDSM_X4(ah[0],ah[1],ah[2],ah[3], aArbH + (cA ^ aArx));
            LDSM_X4(al[0],al[1],al[2],al[3], aArbL + (cA ^ aArx));
            const uint32_t cB = (uint32_t)(2*ks + hB)*16;
            #pragma unroll
            for (int nbp = 0; nbp < 4; nbp++) {
                const uint32_t rbB = (uint32_t)(nbp*16 + rBo)*256 + (cB ^ bBrx);
                uint32_t bh[4], bl[4];
                LDSM_X4(bh[0],bh[1],bh[2],bh[3], smem + SM_BH + rbB);
                LDSM_X4(bl[0],bl[1],bl[2],bl[3], smem + SM_BL + rbB);
                MMA16816(acc[2*nbp],   ah, bh[0], bh[1]);
                MMA16816(acc[2*nbp+1], ah, bh[2], bh[3]);
                MMA16816(acc[2*nbp],   ah, bl[0], bl[1]);
                MMA16816(acc[2*nbp+1], ah, bl[2], bl[3]);
                MMA16816(acc[2*nbp],   al, bh[0], bh[1]);
                MMA16816(acc[2*nbp+1], al, bh[2], bh[3]);
            }
        }
        __syncthreads();   // all ldmatrix reads done before next stage/build
    }

    // ---- epilogue: scatter live fragments to g_S (nb==7 / vv==7 are dead)
    const int m0 = w*16;
    #pragma unroll
    for (int nb = 0; nb < 7; nb++) {
        const int ncol = nb*8 + 2*(lane & 3);
        #pragma unroll
        for (int hf = 0; hf < 2; hf++) {
            int m = m0 + (lane >> 2) + hf*8;
            int qc = m >> 4, pq = m & 15;
            float* So = g_S + ((((b*3+i)*8 + qc)*3 + c)*784 + pq*49);
            #pragma unroll
            for (int e = 0; e < 2; e++) {
                int n = ncol + e;
                int vv = n & 7;
                if (vv < 7) So[nb*7 + vv] = acc[nb][hf*2 + e];
            }
        }
    }
}

// ===========================================================================
// Kernel Qs: clipped window sums of q. grid 384 = (b,i,qc)
// ===========================================================================
__global__ __launch_bounds__(128) void k_qs()
{
    __shared__ float cs[4][114];
    const int bx = blockIdx.x;
    const float* Q = g_q + bx*H2*H2;
    const int tid = threadIdx.x;
    if (tid < 112) {
        float full=0.f, e0=0.f,e1=0.f,e2=0.f,e109=0.f,e110=0.f,e111=0.f;
        for (int y = 0; y < 112; y++) {
            float v = Q[y*H2 + tid];
            full += v;
            if (y==0) e0=v; else if (y==1) e1=v; else if (y==2) e2=v;
            else if (y==109) e109=v; else if (y==110) e110=v; else if (y==111) e111=v;
        }
        cs[0][tid] = full - e109 - e110 - e111;
        cs[1][tid] = full - e111;
        cs[2][tid] = full - e0;
        cs[3][tid] = full - e0 - e1 - e2;
    }
    __syncthreads();
    if (tid < 16) {
        int p = tid >> 2, qx = tid & 3;
        int xs_ = (qx <= 1) ? 0 : (qx == 2 ? 1 : 3);
        int xe_ = (qx == 0) ? 109 : (qx == 1 ? 111 : 112);
        float s = 0.f;
        for (int xc = xs_; xc < xe_; xc++) s += cs[p][xc];
        g_Qs[bx*16 + tid] = s;
    }
}

// ===========================================================================
// Kernel a: grid 768 = (b,i,vc); 256 thr = 16 K-slices x 16 pq
// ===========================================================================
__global__ __launch_bounds__(256) void k_a(const float* __restrict__ Wk,
                                           const float* __restrict__ bk)
{
    const int bx = blockIdx.x;
    const int vc = bx & 15, bi = bx >> 4;
    const int i = bi % 3;
    const int tid = threadIdx.x;
    const int s = tid & 15, pq = tid >> 4;
    const float* Sb = g_S + bi*24*784;
    const float* Wb = Wk + i*(VCn*QCn*ICn*49) + vc*(QCn*ICn*49);
    float acc = 0.f;
    #pragma unroll 1
    for (int qcc = 0; qcc < 24; qcc++) {
        const float* Sp = Sb + qcc*784 + pq*49;
        const float* Wp = Wb + qcc*49;
        #pragma unroll
        for (int uv = s; uv < 49; uv += 16) acc += Wp[uv]*Sp[uv];
    }
    #pragma unroll
    for (int o = 8; o; o >>= 1) acc += __shfl_down_sync(0xffffffffu, acc, o, 16);
    if (s == 0) {
        const float* Qsb = g_Qs + bi*8*16;
        float bterm = 0.f;
        #pragma unroll
        for (int qc = 0; qc < 8; qc++)
            bterm += bk[(i*16+vc)*8+qc] * Qsb[qc*16+pq];
        g_a[bi*256 + vc*16 + pq] = acc + bterm;
    }
}

// ===========================================================================
// Kernel o: o[b,i,58,58] = dynconv(v[b], a[b,i]); grid (48, 14)
// ===========================================================================
__global__ __launch_bounds__(256) void k_o(float* __restrict__ out)
{
    __shared__ float as_[256];
    const int bx = blockIdx.x;
    const int b = bx/3;
    const int tid = threadIdx.x;
    as_[tid] = g_a[bx*256 + tid];
    __syncthreads();

    const int idx = blockIdx.y*256 + tid;
    if (idx >= 58*58) return;
    const int oy = idx/58, ox = idx%58;
    const float* vb = g_v + b*16*H2*H2;
    float acc = 0.f;
    for (int vc = 0; vc < 16; vc++) {
        const float* vp = vb + vc*H2*H2;
        const float* ap = &as_[vc*16];
        #pragma unroll
        for (int ky = 0; ky < 4; ky++) {
            int r = 2*oy - 3 + ky;
            if (r < 0 || r >= H2) continue;
            #pragma unroll
            for (int kx = 0; kx < 4; kx++) {
                int cc = 2*ox - 3 + kx;
                if (cc < 0 || cc >= H2) continue;
                acc += ap[ky*4+kx] * vp[r*H2 + cc];
            }
        }
    }
    out[bx*3364 + idx] = acc;
}

extern "C" void kernel_launch(void* const* d_in, const int* in_sizes, int n_in,
                              void* d_out, int out_size)
{
    const float* x  = (const float*)d_in[0];
    const float* Wq = (const float*)d_in[1];
    const float* bq = (const float*)d_in[2];
    const float* Wk = (const float*)d_in[3];
    const float* bk = (const float*)d_in[4];
    const float* Wv = (const float*)d_in[5];
    const float* bv = (const float*)d_in[6];
    float* out = (float*)d_out;

    cudaFuncSetAttribute(k_S_mma, cudaFuncAttributeMaxDynamicSharedMemorySize, SM_TOT);

    k_convqv<<<dim3(112,16), 224>>>(x, Wq, bq, Wv, bv);
    k_cvt_q <<<384, 256>>>();
    k_cvt_x <<<48, 256>>>(x);
    k_S_mma <<<144, 256, SM_TOT>>>();
    k_qs    <<<384, 128>>>();
    k_a     <<<768, 256>>>(Wk, bk);
    k_o     <<<dim3(48,14), 256>>>(out);
}

// round 12
// speedup vs baseline: 2.8134x; 1.6691x over previous
#include <cuda_runtime.h>
#include <cuda_bf16.h>
#include <stdint.h>

typedef unsigned long long ull;

#define Bn  16
#define ICn 3
#define QCn 8
#define VCn 16
#define Hn  224
#define Wn  224
#define H2  112

// ---- scratch: device globals (no runtime allocation allowed) ----
__device__ float g_q [Bn*24*H2*H2];          // [b][i*8+qc][112][112]
__device__ float g_v [Bn*16*H2*H2];          // [b][vc][112][112]
__device__ float g_S [1152*784];             // [(b,i,qc,c)][pq*49+uv]
__device__ float g_Qs[Bn*ICn*QCn*16];        // [(b,i,qc)][pq]
__device__ float g_a [Bn*ICn*VCn*16];        // [(b,i)][vc*16+pq]
// Pre-shifted bf16 operands, rows padded to 128 elems (256 B):
//  g_qsh[qp][mat][(b,i,qc)][y][j] = hi/lo( q_pad[y][j+2qp] )     (88 MB)
//  g_xsh[v ][mat][(b,c)  ][y][j] = hi/lo( x_pad[y][2j+v] )       (38.5 MB)
__device__ __align__(16) __nv_bfloat16 g_qsh[4*2*384*112*128];
__device__ __align__(16) __nv_bfloat16 g_xsh[7*2*48*224*128];

#define QSH_MATSTRIDE 11010048   // 384*112*256 bytes
#define QSH_QCSTRIDE  28672      // 112*256
#define XSH_MATSTRIDE 2752512    // 48*224*256 bytes
#define XSH_BCSTRIDE  57344      // 224*256

#define FMA2(d,a,b) asm("fma.rn.f32x2 %0, %1, %2, %0;" : "+l"(d) : "l"(a), "l"(b))
#define DUP2(d,s)   asm("mov.b64 %0, {%1, %1};" : "=l"(d) : "f"(s))

__device__ __forceinline__ uint32_t smem_to_u32(const void* p) {
    uint32_t a;
    asm("{ .reg .u64 t; cvta.to.shared.u64 t, %1; cvt.u32.u64 %0, t; }" : "=r"(a) : "l"(p));
    return a;
}

#define LDSM_X4(r0,r1,r2,r3,addr) \
    asm volatile("ldmatrix.sync.aligned.m8n8.x4.shared.b16 {%0,%1,%2,%3}, [%4];" \
        : "=r"(r0),"=r"(r1),"=r"(r2),"=r"(r3) : "r"(addr))

#define MMA16816(d,a,b0,b1) \
    asm volatile("mma.sync.aligned.m16n8k16.row.col.f32.bf16.bf16.f32 " \
        "{%0,%1,%2,%3}, {%4,%5,%6,%7}, {%8,%9}, {%0,%1,%2,%3};" \
        : "+f"((d)[0]),"+f"((d)[1]),"+f"((d)[2]),"+f"((d)[3]) \
        : "r"((a)[0]),"r"((a)[1]),"r"((a)[2]),"r"((a)[3]), "r"(b0),"r"(b1))

#define CP_ASYNC16(dst, src, sz) \
    asm volatile("cp.async.cg.shared.global [%0], [%1], 16, %2;" \
        :: "r"(dst), "l"(src), "r"(sz) : "memory")
#define CP_COMMIT()  asm volatile("cp.async.commit_group;" ::: "memory")
#define CP_WAIT1()   asm volatile("cp.async.wait_group 1;" ::: "memory")
#define CP_WAIT0()   asm volatile("cp.async.wait_group 0;" ::: "memory")

// ===========================================================================
// Kernel A: fused static convs q (24 ch) + v (16 ch), stride 2, pad 3.
// ===========================================================================
__global__ __launch_bounds__(224) void k_convqv(
    const float* __restrict__ x,
    const float* __restrict__ Wq, const float* __restrict__ bq,
    const float* __restrict__ Wv, const float* __restrict__ bv)
{
    __shared__ __align__(16) float xs[3*7*232];
    __shared__ __align__(16) float ws[147*40];
    __shared__ __align__(16) float bs[40];
    const int oy = blockIdx.x, b = blockIdx.y;
    const int tid = threadIdx.x;

    for (int t = tid; t < 24*147; t += 224) { int oc=t/147, cuv=t%147; ws[cuv*40+oc]    = Wq[t]; }
    for (int t = tid; t < 16*147; t += 224) { int oc=t/147, cuv=t%147; ws[cuv*40+24+oc] = Wv[t]; }
    if (tid < 24) bs[tid] = bq[tid];
    else if (tid < 40) bs[tid] = bv[tid-24];

    const float* xb = x + b*ICn*Hn*Wn;
    for (int t = tid; t < 3*7*232; t += 224) {
        int cc = t/(7*232), r = (t/232)%7, j = t%232;
        int row = 2*oy - 3 + r, col = j - 3;
        float v = 0.f;
        if (row >= 0 && row < Hn && col >= 0 && col < Wn) v = xb[(cc*Hn+row)*Wn + col];
        xs[t] = v;
    }
    __syncthreads();

    const int half = tid/112, ox = tid%112;
    ull acc2[10];
    {
        const float2* b2 = reinterpret_cast<const float2*>(bs + half*20);
        #pragma unroll
        for (int k = 0; k < 10; k++) {
            float2 t = b2[k];
            asm("mov.b64 %0, {%1, %2};" : "=l"(acc2[k]) : "f"(t.x), "f"(t.y));
        }
    }
    #pragma unroll 1
    for (int cc = 0; cc < 3; cc++)
      #pragma unroll 1
      for (int u = 0; u < 7; u++) {
        const float* xr = &xs[(cc*7+u)*232 + 2*ox];
        const ull*  wr = reinterpret_cast<const ull*>(&ws[(cc*49+u*7)*40 + half*20]);
        #pragma unroll
        for (int v = 0; v < 7; v++) {
            ull xd; DUP2(xd, xr[v]);
            #pragma unroll
            for (int k = 0; k < 10; k++) FMA2(acc2[k], xd, wr[v*20 + k]);
        }
      }
    #pragma unroll
    for (int k = 0; k < 10; k++) {
        float2 f = *reinterpret_cast<float2*>(&acc2[k]);
        int oc0 = half*20 + 2*k;
        #pragma unroll
        for (int h = 0; h < 2; h++) {
            int oc = oc0 + h;
            float val = h ? f.y : f.x;
            if (oc < 24) g_q[((b*24 + oc)*H2 + oy)*H2 + ox]      = val;
            else         g_v[((b*16 + (oc-24))*H2 + oy)*H2 + ox] = val;
        }
    }
}

// ===========================================================================
// Pre-pass: q -> 4 shifted bf16 hi/lo copies. grid (384, 4=qp)
// qsh[qp][..][y][j] = q_pad[y][j+2qp]; q_pad col jj maps to q[jj-3] for 3<=jj<115
// ===========================================================================
__global__ __launch_bounds__(256) void k_cvt_q()
{
    const int bx = blockIdx.x, qp = blockIdx.y;
    const float* Q = g_q + bx*H2*H2;
    __nv_bfloat16* oh = g_qsh + ((size_t)(qp*2+0)*384 + bx)*112*128;
    __nv_bfloat16* ol = g_qsh + ((size_t)(qp*2+1)*384 + bx)*112*128;
    for (int t = threadIdx.x; t < 112*128; t += 256) {
        int y = t >> 7, j = t & 127;
        int jj = j + 2*qp;
        float v = (jj >= 3 && jj < 115) ? Q[y*H2 + (jj-3)] : 0.f;
        __nv_bfloat16 h = __float2bfloat16(v);
        oh[t] = h;
        ol[t] = __float2bfloat16(v - __bfloat162float(h));
    }
}

// Pre-pass: x -> 7 phase-deinterleaved bf16 hi/lo copies. grid (48, 7=v)
// xsh[v][..][y][j] = x_pad[y][2j+v]
__global__ __launch_bounds__(256) void k_cvt_x(const float* __restrict__ x)
{
    const int bc = blockIdx.x, v = blockIdx.y;
    const float* X = x + bc*Hn*Wn;
    __nv_bfloat16* oh = g_xsh + ((size_t)(v*2+0)*48 + bc)*224*128;
    __nv_bfloat16* ol = g_xsh + ((size_t)(v*2+1)*48 + bc)*224*128;
    for (int t = threadIdx.x; t < 224*128; t += 256) {
        int y = t >> 7, j = t & 127;
        int col = 2*j + v;
        float val = (col >= 3 && col < 227) ? X[y*Wn + (col-3)] : 0.f;
        __nv_bfloat16 h = __float2bfloat16(val);
        oh[t] = h;
        ol[t] = __float2bfloat16(val - __bfloat162float(h));
    }
}

// ===========================================================================
// Kernel S via mma.sync, cp.async double-buffered.
// per (b,i,c): D[128,64] = A.B^T over K=(ky,kx)=12544, fp32 accum in regs.
// Tiles filled straight from pre-shifted globals with aligned 16B cp.async.
// ===========================================================================
#define SM_AH    0
#define SM_AL    32768
#define SM_BH    65536
#define SM_BL    81920
#define BUFSTRIDE 98304
#define SM_TOT   (2*BUFSTRIDE)    // 192 KB

extern __shared__ char dsm[];

__device__ __forceinline__ void fill_tiles(uint32_t smem, uint32_t bufbase,
        int ky, int tid, const char* qbase, const char* xbase)
{
    // A: 2 mats x 128 rows x 16 chunks = 4096 cp.asyncs (chunks 14,15 are pad)
    #pragma unroll
    for (int k = 0; k < 16; k++) {
        int idx = tid + 256*k;
        int ch = idx & 15, m = (idx >> 4) & 127, mat = idx >> 11;
        int qp = m & 3, p = (m >> 2) & 3, qc = m >> 4;
        int r = ky + 2*p - 3;
        unsigned ok = ((unsigned)r < 112u);
        const char* src = qbase + (qp*2+mat)*QSH_MATSTRIDE + qc*QSH_QCSTRIDE
                        + (ok ? r : 0)*256 + ch*16;
        uint32_t dst = smem + bufbase + (mat ? SM_AL : SM_AH)
                     + m*256 + ((ch ^ (m & 7))*16);
        CP_ASYNC16(dst, src, ok ? 16u : 0u);
    }
    // B: 2 mats x 64 rows x 16 chunks = 2048 (dead rows zero-filled)
    #pragma unroll
    for (int k = 0; k < 8; k++) {
        int idx = tid + 256*k;
        int ch = idx & 15, n = (idx >> 4) & 63, mat = idx >> 10;
        int u = n >> 3, v = n & 7;
        int r = 2*ky - 3 + u;
        unsigned ok = (v < 7) && (u < 7) && ((unsigned)r < 224u);
        const char* src = xbase + ((ok ? v : 0)*2+mat)*XSH_MATSTRIDE
                        + (ok ? r : 0)*256 + ch*16;
        uint32_t dst = smem + bufbase + (mat ? SM_BL : SM_BH)
                     + n*256 + ((ch ^ (n & 7))*16);
        CP_ASYNC16(dst, src, ok ? 16u : 0u);
    }
}

__global__ __launch_bounds__(256) void k_S_mma()
{
    const uint32_t smem = smem_to_u32(dsm);
    const int tid = threadIdx.x, w = tid >> 5, lane = tid & 31;
    const int bx = blockIdx.x;               // 144 = (b,i,c), c fastest
    const int c = bx % 3, i = (bx/3) % 3, b = bx/9;
    const int bi8 = (b*3 + i)*8, bc = b*3 + c;

    const char* qbase = (const char*)g_qsh + (size_t)bi8*QSH_QCSTRIDE;
    const char* xbase = (const char*)g_xsh + (size_t)bc*XSH_BCSTRIDE;

    float acc[8][4];
    #pragma unroll
    for (int n = 0; n < 8; n++)
      #pragma unroll
      for (int e = 0; e < 4; e++) acc[n][e] = 0.f;

    // per-thread ldmatrix address components (buffer-relative)
    const int rA = w*16 + (lane & 15);
    const uint32_t aAoff = rA*256;
    const uint32_t aArx  = (rA & 7)*16;
    const int hA = (lane >> 4) & 1;
    const int rBo = (lane & 7) + ((lane & 16) >> 1);
    const uint32_t bBrx = (lane & 7)*16;
    const int hB = (lane >> 3) & 1;

    fill_tiles(smem, 0, 0, tid, qbase, xbase);          CP_COMMIT();
    fill_tiles(smem, BUFSTRIDE, 1, tid, qbase, xbase);  CP_COMMIT();

    for (int ky = 0; ky < 112; ky++) {
        if (ky == 111) { CP_WAIT0(); } else { CP_WAIT1(); }
        __syncthreads();                  // buf[ky&1] visible to all warps

        const uint32_t base = smem + (uint32_t)(ky & 1)*BUFSTRIDE;
        const uint32_t aAddrH = base + SM_AH + aAoff;
        const uint32_t aAddrL = base + SM_AL + aAoff;

        #pragma unroll 1
        for (int ks = 0; ks < 7; ks++) {
            const uint32_t cA = (uint32_t)(2*ks + hA)*16;
            uint32_t ah[4], al[4];
            LDSM_X4(ah[0],ah[1],ah[2],ah[3], aAddrH + (cA ^ aArx));
            LDSM_X4(al[0],al[1],al[2],al[3], aAddrL + (cA ^ aArx));
            const uint32_t cB = (uint32_t)(2*ks + hB)*16;
            #pragma unroll
            for (int nbp = 0; nbp < 4; nbp++) {
                const uint32_t rbB = (uint32_t)(nbp*16 + rBo)*256 + (cB ^ bBrx);
                uint32_t bh[4], bl[4];
                LDSM_X4(bh[0],bh[1],bh[2],bh[3], base + SM_BH + rbB);
                LDSM_X4(bl[0],bl[1],bl[2],bl[3], base + SM_BL + rbB);
                MMA16816(acc[2*nbp],   ah, bh[0], bh[1]);
                MMA16816(acc[2*nbp+1], ah, bh[2], bh[3]);
                MMA16816(acc[2*nbp],   ah, bl[0], bl[1]);
                MMA16816(acc[2*nbp+1], ah, bl[2], bl[3]);
                MMA16816(acc[2*nbp],   al, bh[0], bh[1]);
                MMA16816(acc[2*nbp+1], al, bh[2], bh[3]);
            }
        }
        __syncthreads();                  // all reads of buf[ky&1] done
        if (ky + 2 < 112) {
            fill_tiles(smem, (uint32_t)(ky & 1)*BUFSTRIDE, ky + 2, tid, qbase, xbase);
            CP_COMMIT();
        }
    }

    // ---- epilogue: scatter live fragments to g_S (nb==7 / vv==7 are dead)
    const int m0 = w*16;
    #pragma unroll
    for (int nb = 0; nb < 7; nb++) {
        const int ncol = nb*8 + 2*(lane & 3);
        #pragma unroll
        for (int hf = 0; hf < 2; hf++) {
            int m = m0 + (lane >> 2) + hf*8;
            int qc = m >> 4, pq = m & 15;
            float* So = g_S + ((((b*3+i)*8 + qc)*3 + c)*784 + pq*49);
            #pragma unroll
            for (int e = 0; e < 2; e++) {
                int n = ncol + e;
                int vv = n & 7;
                if (vv < 7) So[nb*7 + vv] = acc[nb][hf*2 + e];
            }
        }
    }
}

// ===========================================================================
// Kernel Qs: clipped window sums of q. grid 384 = (b,i,qc)
// ===========================================================================
__global__ __launch_bounds__(128) void k_qs()
{
    __shared__ float cs[4][114];
    const int bx = blockIdx.x;
    const float* Q = g_q + bx*H2*H2;
    const int tid = threadIdx.x;
    if (tid < 112) {
        float full=0.f, e0=0.f,e1=0.f,e2=0.f,e109=0.f,e110=0.f,e111=0.f;
        for (int y = 0; y < 112; y++) {
            float v = Q[y*H2 + tid];
            full += v;
            if (y==0) e0=v; else if (y==1) e1=v; else if (y==2) e2=v;
            else if (y==109) e109=v; else if (y==110) e110=v; else if (y==111) e111=v;
        }
        cs[0][tid] = full - e109 - e110 - e111;
        cs[1][tid] = full - e111;
        cs[2][tid] = full - e0;
        cs[3][tid] = full - e0 - e1 - e2;
    }
    __syncthreads();
    if (tid < 16) {
        int p = tid >> 2, qx = tid & 3;
        int xs_ = (qx <= 1) ? 0 : (qx == 2 ? 1 : 3);
        int xe_ = (qx == 0) ? 109 : (qx == 1 ? 111 : 112);
        float s = 0.f;
        for (int xc = xs_; xc < xe_; xc++) s += cs[p][xc];
        g_Qs[bx*16 + tid] = s;
    }
}

// ===========================================================================
// Kernel a: grid 768 = (b,i,vc); 256 thr = 16 K-slices x 16 pq
// ===========================================================================
__global__ __launch_bounds__(256) void k_a(const float* __restrict__ Wk,
                                           const float* __restrict__ bk)
{
    const int bx = blockIdx.x;
    const int vc = bx & 15, bi = bx >> 4;
    const int i = bi % 3;
    const int tid = threadIdx.x;
    const int s = tid & 15, pq = tid >> 4;
    const float* Sb = g_S + bi*24*784;
    const float* Wb = Wk + i*(VCn*QCn*ICn*49) + vc*(QCn*ICn*49);
    float acc = 0.f;
    #pragma unroll 1
    for (int qcc = 0; qcc < 24; qcc++) {
        const float* Sp = Sb + qcc*784 + pq*49;
        const float* Wp = Wb + qcc*49;
        #pragma unroll
        for (int uv = s; uv < 49; uv += 16) acc += Wp[uv]*Sp[uv];
    }
    #pragma unroll
    for (int o = 8; o; o >>= 1) acc += __shfl_down_sync(0xffffffffu, acc, o, 16);
    if (s == 0) {
        const float* Qsb = g_Qs + bi*8*16;
        float bterm = 0.f;
        #pragma unroll
        for (int qc = 0; qc < 8; qc++)
            bterm += bk[(i*16+vc)*8+qc] * Qsb[qc*16+pq];
        g_a[bi*256 + vc*16 + pq] = acc + bterm;
    }
}

// ===========================================================================
// Kernel o: o[b,i,58,58] = dynconv(v[b], a[b,i]); grid (48, 14)
// ===========================================================================
__global__ __launch_bounds__(256) void k_o(float* __restrict__ out)
{
    __shared__ float as_[256];
    const int bx = blockIdx.x;
    const int b = bx/3;
    const int tid = threadIdx.x;
    as_[tid] = g_a[bx*256 + tid];
    __syncthreads();

    const int idx = blockIdx.y*256 + tid;
    if (idx >= 58*58) return;
    const int oy = idx/58, ox = idx%58;
    const float* vb = g_v + b*16*H2*H2;
    float acc = 0.f;
    for (int vc = 0; vc < 16; vc++) {
        const float* vp = vb + vc*H2*H2;
        const float* ap = &as_[vc*16];
        #pragma unroll
        for (int ky = 0; ky < 4; ky++) {
            int r = 2*oy - 3 + ky;
            if (r < 0 || r >= H2) continue;
            #pragma unroll
            for (int kx = 0; kx < 4; kx++) {
                int cc = 2*ox - 3 + kx;
                if (cc < 0 || cc >= H2) continue;
                acc += ap[ky*4+kx] * vp[r*H2 + cc];
            }
        }
    }
    out[bx*3364 + idx] = acc;
}

extern "C" void kernel_launch(void* const* d_in, const int* in_sizes, int n_in,
                              void* d_out, int out_size)
{
    const float* x  = (const float*)d_in[0];
    const float* Wq = (const float*)d_in[1];
    const float* bq = (const float*)d_in[2];
    const float* Wk = (const float*)d_in[3];
    const float* bk = (const float*)d_in[4];
    const float* Wv = (const float*)d_in[5];
    const float* bv = (const float*)d_in[6];
    float* out = (float*)d_out;

    cudaFuncSetAttribute(k_S_mma, cudaFuncAttributeMaxDynamicSharedMemorySize, SM_TOT);

    k_convqv<<<dim3(112,16), 224>>>(x, Wq, bq, Wv, bv);
    k_cvt_q <<<dim3(384,4), 256>>>();
    k_cvt_x <<<dim3(48,7), 256>>>(x);
    k_S_mma <<<144, 256, SM_TOT>>>();
    k_qs    <<<384, 128>>>();
    k_a     <<<768, 256>>>(Wk, bk);
    k_o     <<<dim3(48,14), 256>>>(out);
}